// round 1
// baseline (speedup 1.0000x reference)
#include <cuda_runtime.h>

// Problem constants (fixed shapes from setup_inputs)
#define BB 4
#define CC 256
#define HH 96
#define WW 320
#define HW (HH * WW)          // 30720, stride between channels
#define QT 64                 // queries per CTA
#define KC 8                  // K-chunk depth
#define NTH 256
#define NLVL 4
#define RAD 4
#define NCH 36                // 4 levels * 9 taps

#define VOL_STRIDE 322        // 320 + 2 pad (even, breaks bank alignment)
#define SMEM_FLOATS (KC * QT + KC * WW + QT * VOL_STRIDE)
#define SMEM_BYTES (SMEM_FLOATS * 4)

// ---- packed f32x2 helpers (sm_103a FFMA2 path; ptxas never emits this from C++) ----
__device__ __forceinline__ unsigned long long pack2(float x, float y) {
    unsigned long long r;
    asm("mov.b64 %0, {%1, %2};" : "=l"(r) : "f"(x), "f"(y));
    return r;
}
__device__ __forceinline__ unsigned long long fma2(unsigned long long a,
                                                   unsigned long long b,
                                                   unsigned long long c) {
    unsigned long long r;
    asm("fma.rn.f32x2 %0, %1, %2, %3;" : "=l"(r) : "l"(a), "l"(b), "l"(c));
    return r;
}
__device__ __forceinline__ void unpack2(unsigned long long v, float& x, float& y) {
    asm("mov.b64 {%0, %1}, %2;" : "=f"(x), "=f"(y) : "l"(v));
}

// Pooled value at level lvl, index i, with zero padding outside [0, Wl).
// Equals the reference's iterated (1,2)-avg-pool up to fp reassociation (~1e-7).
__device__ __forceinline__ float pooled(const float* __restrict__ row, int i, int lvl, int Wl) {
    if (i < 0 || i >= Wl) return 0.0f;
    const int sz = 1 << lvl;
    const float* p = row + (i << lvl);
    float s = 0.0f;
#pragma unroll 8
    for (int k = 0; k < sz; ++k) s += p[k];
    return s * (1.0f / (float)sz);
}

__global__ void __launch_bounds__(NTH)
corrblock_fused_kernel(const float* __restrict__ fmap1,
                       const float* __restrict__ fmap2,
                       const float* __restrict__ cents,
                       float* __restrict__ out) {
    extern __shared__ float smem[];
    float* sA  = smem;                  // [KC][QT]
    float* sB  = smem + KC * QT;        // [KC][WW]
    float* vol = smem + KC * QT + KC * WW;  // [QT][VOL_STRIDE]

    const int qtile = blockIdx.x;
    const int h     = blockIdx.y;
    const int b     = blockIdx.z;
    const int q0    = qtile * QT;

    const int t  = threadIdx.x;
    const int ty = t >> 5;   // 0..7
    const int tx = t & 31;   // 0..31

    const float* Abase = fmap1 + (size_t)b * CC * HW + h * WW + q0;
    const float* Bbase = fmap2 + (size_t)b * CC * HW + h * WW;

    // ---- B-chunk load mapping (fixed per thread) ----
    int cB[5], colB[5];
#pragma unroll
    for (int j = 0; j < 5; ++j) {
        int p = 2 * t + 512 * j;       // 0..2558, pairs never cross a 320-row
        cB[j]   = p / 320;             // 0..7
        colB[j] = p - cB[j] * 320;
    }

    // ---- accumulators: 8 queries x 5 value-pairs, packed f32x2 ----
    unsigned long long acc[8][5];
#pragma unroll
    for (int i = 0; i < 8; ++i)
#pragma unroll
        for (int j = 0; j < 5; ++j) acc[i][j] = 0ULL;

    // ---- register-prefetch double buffering over 32 K-chunks ----
    float2 ra;
    float2 rb[5];

    // prefetch chunk 0
    {
        ra = *(const float2*)(Abase + (0 * KC + ty) * HW + 2 * tx);
#pragma unroll
        for (int j = 0; j < 5; ++j)
            rb[j] = *(const float2*)(Bbase + (0 * KC + cB[j]) * HW + colB[j]);
    }

    const int NCHUNK = CC / KC;  // 32
    for (int kc = 0; kc < NCHUNK; ++kc) {
        __syncthreads();  // previous compute done -> smem free
        *(float2*)&sA[ty * QT + 2 * tx] = ra;
#pragma unroll
        for (int j = 0; j < 5; ++j)
            *(float2*)&sB[cB[j] * WW + colB[j]] = rb[j];
        __syncthreads();

        if (kc + 1 < NCHUNK) {
            ra = *(const float2*)(Abase + ((kc + 1) * KC + ty) * HW + 2 * tx);
#pragma unroll
            for (int j = 0; j < 5; ++j)
                rb[j] = *(const float2*)(Bbase + ((kc + 1) * KC + cB[j]) * HW + colB[j]);
        }

#pragma unroll
        for (int k = 0; k < KC; ++k) {
            // 8 query values for this thread (q = 8*ty + i), broadcast within warp
            float4 a03 = *(const float4*)&sA[k * QT + ty * 8];
            float4 a47 = *(const float4*)&sA[k * QT + ty * 8 + 4];
            unsigned long long aa[8];
            aa[0] = pack2(a03.x, a03.x);
            aa[1] = pack2(a03.y, a03.y);
            aa[2] = pack2(a03.z, a03.z);
            aa[3] = pack2(a03.w, a03.w);
            aa[4] = pack2(a47.x, a47.x);
            aa[5] = pack2(a47.y, a47.y);
            aa[6] = pack2(a47.z, a47.z);
            aa[7] = pack2(a47.w, a47.w);
            unsigned long long bb[5];
#pragma unroll
            for (int j = 0; j < 5; ++j)
                bb[j] = *(const unsigned long long*)&sB[k * WW + 2 * tx + 64 * j];
#pragma unroll
            for (int i = 0; i < 8; ++i)
#pragma unroll
                for (int j = 0; j < 5; ++j)
                    acc[i][j] = fma2(aa[i], bb[j], acc[i][j]);
        }
    }

    // ---- epilogue: store scaled corr slice to smem vol ----
    __syncthreads();
    const float scale = 0.0625f;  // 1/sqrt(256)
#pragma unroll
    for (int i = 0; i < 8; ++i) {
        int q = ty * 8 + i;
#pragma unroll
        for (int j = 0; j < 5; ++j) {
            float x, y;
            unpack2(acc[i][j], x, y);
            int v = 2 * tx + 64 * j;
            *(float2*)&vol[q * VOL_STRIDE + v] = make_float2(x * scale, y * scale);
        }
    }
    __syncthreads();

    // ---- sampling: 64 q x 36 channels, 9 outputs per thread ----
    const int q     = t & 63;
    const int chgrp = t >> 6;  // 0..3
    const float cent = cents[((size_t)b * HH + h) * WW + q0 + q];
    const float* row = &vol[q * VOL_STRIDE];

#pragma unroll
    for (int rep = 0; rep < 9; ++rep) {
        const int ch  = chgrp + 4 * rep;  // covers 0..35
        const int lvl = ch / 9;
        const int tap = ch - lvl * 9;
        const int Wl  = WW >> lvl;
        const float x  = cent * (1.0f / (float)(1 << lvl)) + (float)(tap - RAD);
        const float x0 = floorf(x);
        const float tt = x - x0;
        const int   i0 = (int)x0;
        const float p0 = pooled(row, i0,     lvl, Wl);
        const float p1 = pooled(row, i0 + 1, lvl, Wl);
        const float res = p0 * (1.0f - tt) + p1 * tt;
        out[(((size_t)b * NCH + ch) * HH + h) * WW + q0 + q] = res;
    }
}

extern "C" void kernel_launch(void* const* d_in, const int* in_sizes, int n_in,
                              void* d_out, int out_size) {
    const float* fmap1 = (const float*)d_in[0];
    const float* fmap2 = (const float*)d_in[1];
    const float* cents = (const float*)d_in[2];
    float* out = (float*)d_out;

    cudaFuncSetAttribute(corrblock_fused_kernel,
                         cudaFuncAttributeMaxDynamicSharedMemorySize, SMEM_BYTES);

    dim3 grid(WW / QT, HH, BB);  // (5, 96, 4): q-tile fastest => fmap2 row reused in L2
    corrblock_fused_kernel<<<grid, NTH, SMEM_BYTES>>>(fmap1, fmap2, cents, out);
}

// round 4
// speedup vs baseline: 2.0363x; 2.0363x over previous
#include <cuda_runtime.h>
#include <cstdint>

// ---------------- problem constants ----------------
#define BB 4
#define CC 256
#define HH 96
#define WW 320
#define HW (HH * WW)          // 30720
#define MT 64                 // queries per CTA
#define KC 16                 // K per chunk (one mma k-step)
#define NCHUNK (CC / KC)      // 16
#define NTH 256
#define RAD 4
#define NCH 36
#define VOL_STRIDE 322        // even (float2-aligned), 2 mod 4 limits conflicts

// ---------------- smem layout (bytes) ----------------
#define BSTR 656              // B row stride: 328 halves (16B-aligned, conflict-free)
#define ASTR 176              // A row stride: 88 halves
#define OFF_BH 0
#define OFF_BL (KC * BSTR)            // 10496
#define OFF_AH (2 * KC * BSTR)        // 20992
#define OFF_AL (OFF_AH + KC * ASTR)   // 23808
#define STAGE_BYTES (OFF_AL + KC * ASTR)       // 26624
#define VOL_BYTES (MT * VOL_STRIDE * 4)        // 82432
#define SMEM_BYTES (VOL_BYTES)                 // vol overlays stage after mainloop

static __device__ __forceinline__ uint32_t smem_u32(const void* p) {
    uint32_t a;
    asm("{ .reg .u64 t; cvta.to.shared.u64 t, %1; cvt.u32.u64 %0, t; }" : "=r"(a) : "l"(p));
    return a;
}

static __device__ __forceinline__ void ldsm4t(uint32_t* r, uint32_t a) {
    asm volatile("ldmatrix.sync.aligned.m8n8.x4.trans.shared.b16 {%0,%1,%2,%3}, [%4];"
                 : "=r"(r[0]), "=r"(r[1]), "=r"(r[2]), "=r"(r[3]) : "r"(a));
}
static __device__ __forceinline__ void ldsm2t(uint32_t* r, uint32_t a) {
    asm volatile("ldmatrix.sync.aligned.m8n8.x2.trans.shared.b16 {%0,%1}, [%2];"
                 : "=r"(r[0]), "=r"(r[1]) : "r"(a));
}
static __device__ __forceinline__ void mma16816(float* d, const uint32_t* a, const uint32_t* b) {
    asm volatile("mma.sync.aligned.m16n8k16.row.col.f32.bf16.bf16.f32 "
                 "{%0,%1,%2,%3}, {%4,%5,%6,%7}, {%8,%9}, {%0,%1,%2,%3};"
                 : "+f"(d[0]), "+f"(d[1]), "+f"(d[2]), "+f"(d[3])
                 : "r"(a[0]), "r"(a[1]), "r"(a[2]), "r"(a[3]), "r"(b[0]), "r"(b[1]));
}

// Convert float4 (4 consecutive elements) to hi (exact bf16 truncation) and
// lo (bf16 of residual), store each as one STS.64.
static __device__ __forceinline__ void cvt_sts(uint32_t hi_a, uint32_t lo_a, float4 x) {
    uint32_t u0 = __float_as_uint(x.x), u1 = __float_as_uint(x.y);
    uint32_t u2 = __float_as_uint(x.z), u3 = __float_as_uint(x.w);
    uint32_t h0, h1;
    asm("prmt.b32 %0, %1, %2, 0x7632;" : "=r"(h0) : "r"(u0), "r"(u1));
    asm("prmt.b32 %0, %1, %2, 0x7632;" : "=r"(h1) : "r"(u2), "r"(u3));
    float f0 = x.x - __uint_as_float(u0 & 0xffff0000u);
    float f1 = x.y - __uint_as_float(u1 & 0xffff0000u);
    float f2 = x.z - __uint_as_float(u2 & 0xffff0000u);
    float f3 = x.w - __uint_as_float(u3 & 0xffff0000u);
    uint32_t l0, l1;
    asm("cvt.rn.bf16x2.f32 %0, %1, %2;" : "=r"(l0) : "f"(f1), "f"(f0));
    asm("cvt.rn.bf16x2.f32 %0, %1, %2;" : "=r"(l1) : "f"(f3), "f"(f2));
    asm volatile("st.shared.v2.b32 [%0], {%1,%2};" :: "r"(hi_a), "r"(h0), "r"(h1) : "memory");
    asm volatile("st.shared.v2.b32 [%0], {%1,%2};" :: "r"(lo_a), "r"(l0), "r"(l1) : "memory");
}

__device__ __forceinline__ float pooled(const float* __restrict__ row, int i, int lvl, int Wl) {
    if (i < 0 || i >= Wl) return 0.0f;
    const int sz = 1 << lvl;
    const float* p = row + (i << lvl);
    float s = 0.0f;
#pragma unroll 8
    for (int k = 0; k < sz; ++k) s += p[k];
    return s * (1.0f / (float)sz);
}

__global__ void __launch_bounds__(NTH)
corr_hmma_kernel(const float* __restrict__ fmap1, const float* __restrict__ fmap2,
                 const float* __restrict__ cents, float* __restrict__ out) {
    extern __shared__ char smem[];
    const uint32_t sb = smem_u32(smem);
    const int t = threadIdx.x, wid = t >> 5, lid = t & 31;
    const int q0 = blockIdx.x * MT, h = blockIdx.y, b = blockIdx.z;

    // ---- load mapping: thread -> (channel-in-chunk, float4 position) ----
    const int ch  = t >> 4;   // 0..15
    const int pos = t & 15;   // 0..15
    const float* Ag = fmap1 + ((size_t)b * CC + ch) * HW + (size_t)h * WW + q0 + 4 * pos;
    const float* Bg = fmap2 + ((size_t)b * CC + ch) * HW + (size_t)h * WW + 4 * pos;

    // prefetch chunk 0
    float4 ra = *(const float4*)Ag;
    float4 rb[5];
#pragma unroll
    for (int j = 0; j < 5; ++j) rb[j] = *(const float4*)(Bg + 64 * j);

    // ---- per-lane ldmatrix offsets (trans tiles; stored [k][m] / [k][n]) ----
    const int r8 = lid & 7, tl = lid >> 3;
    const uint32_t laneA = (uint32_t)((r8 + 8 * (tl >> 1)) * ASTR + (tl & 1) * 16);
    const uint32_t laneB = (uint32_t)((r8 + 8 * (tl & 1)) * BSTR + (tl >> 1) * 16);
    const uint32_t nbase = (uint32_t)(80 * wid);  // byte offset for n = 40*wid

    float acc[4][5][4];
#pragma unroll
    for (int i = 0; i < 4; ++i)
#pragma unroll
        for (int j = 0; j < 5; ++j)
#pragma unroll
            for (int k2 = 0; k2 < 4; ++k2) acc[i][j][k2] = 0.0f;

    const uint32_t sts_ah = sb + OFF_AH + (uint32_t)(ch * ASTR + 8 * pos);
    const uint32_t sts_al = sb + OFF_AL + (uint32_t)(ch * ASTR + 8 * pos);
    const uint32_t sts_bh = sb + OFF_BH + (uint32_t)(ch * BSTR + 8 * pos);
    const uint32_t sts_bl = sb + OFF_BL + (uint32_t)(ch * BSTR + 8 * pos);

    for (int kc = 0; kc < NCHUNK; ++kc) {
        __syncthreads();                 // previous compute done with smem
        cvt_sts(sts_ah, sts_al, ra);
#pragma unroll
        for (int j = 0; j < 5; ++j) cvt_sts(sts_bh + 128u * j, sts_bl + 128u * j, rb[j]);
        __syncthreads();                 // stage visible to all warps

        if (kc + 1 < NCHUNK) {           // issue next chunk's LDGs; land during compute
            const size_t o = (size_t)(kc + 1) * KC * HW;
            ra = *(const float4*)(Ag + o);
#pragma unroll
            for (int j = 0; j < 5; ++j) rb[j] = *(const float4*)(Bg + o + 64 * j);
        }

        // 3 split products: (Ah,Bh), (Ah,Bl), (Al,Bh)
#pragma unroll
        for (int p = 0; p < 3; ++p) {
            const uint32_t ab = sb + (p == 2 ? OFF_AL : OFF_AH) + laneA;
            const uint32_t bb = sb + (p == 1 ? OFF_BL : OFF_BH) + laneB + nbase;
            uint32_t a[4][4];
#pragma unroll
            for (int i = 0; i < 4; ++i) ldsm4t(a[i], ab + 32u * i);
            uint32_t bfr[5][2];
            ldsm4t(&bfr[0][0], bb);
            ldsm4t(&bfr[2][0], bb + 32u);
            ldsm2t(&bfr[4][0], bb + 64u);
#pragma unroll
            for (int i = 0; i < 4; ++i)
#pragma unroll
                for (int j = 0; j < 5; ++j) mma16816(acc[i][j], a[i], bfr[j]);
        }
    }

    // ---- accumulators -> vol (overlays stage smem) ----
    __syncthreads();
    float* vol = (float*)smem;
    {
        const int mr = lid >> 2, nc0 = 2 * (lid & 3);
        const float s = 0.0625f;  // 1/sqrt(256)
#pragma unroll
        for (int i = 0; i < 4; ++i)
#pragma unroll
            for (int j = 0; j < 5; ++j) {
                const int q = 16 * i + mr, v = 40 * wid + 8 * j + nc0;
                *(float2*)&vol[q * VOL_STRIDE + v] =
                    make_float2(acc[i][j][0] * s, acc[i][j][1] * s);
                *(float2*)&vol[(q + 8) * VOL_STRIDE + v] =
                    make_float2(acc[i][j][2] * s, acc[i][j][3] * s);
            }
    }
    __syncthreads();

    // ---- pyramid sampling: 64 q x 36 ch, 9 outputs/thread ----
    const int q = t & 63, grp = t >> 6;
    const float cent = cents[((size_t)b * HH + h) * WW + q0 + q];
    const float* row = vol + q * VOL_STRIDE;
#pragma unroll
    for (int rep = 0; rep < 9; ++rep) {
        const int chn = grp + 4 * rep;
        const int lvl = chn / 9, tap = chn - 9 * lvl;
        const int Wl = WW >> lvl;
        const float x  = cent * (1.0f / (float)(1 << lvl)) + (float)(tap - RAD);
        const float x0 = floorf(x);
        const float tt = x - x0;
        const int   i0 = (int)x0;
        const float p0 = pooled(row, i0, lvl, Wl);
        const float p1 = pooled(row, i0 + 1, lvl, Wl);
        out[(((size_t)b * NCH + chn) * HH + h) * WW + q0 + q] = p0 * (1.0f - tt) + p1 * tt;
    }
}

extern "C" void kernel_launch(void* const* d_in, const int* in_sizes, int n_in,
                              void* d_out, int out_size) {
    const float* fmap1 = (const float*)d_in[0];
    const float* fmap2 = (const float*)d_in[1];
    const float* cents = (const float*)d_in[2];
    float* out = (float*)d_out;

    cudaFuncSetAttribute(corr_hmma_kernel,
                         cudaFuncAttributeMaxDynamicSharedMemorySize, SMEM_BYTES);

    dim3 grid(WW / MT, HH, BB);  // (5, 96, 4)
    corr_hmma_kernel<<<grid, NTH, SMEM_BYTES>>>(fmap1, fmap2, cents, out);
}

// round 5
// speedup vs baseline: 2.3495x; 1.1538x over previous
#include <cuda_runtime.h>
#include <cstdint>

// ---------------- problem constants ----------------
#define BB 4
#define CC 256
#define HH 96
#define WW 320
#define HW (HH * WW)          // 30720
#define MT 64                 // queries per CTA
#define KC 16                 // K per chunk (one mma k-step)
#define NCHUNK (CC / KC)      // 16
#define NTH 256
#define RAD 4
#define NCH 36
#define VOL_STRIDE 322

// ---------------- smem layout (bytes) ----------------
#define BSTR 656              // B row stride: 328 halves (16B-aligned, conflict-free)
#define ASTR 176              // A row stride: 88 halves
#define OFF_BH 0
#define OFF_BL (KC * BSTR)            // 10496
#define OFF_AH (2 * KC * BSTR)        // 20992
#define OFF_AL (OFF_AH + KC * ASTR)   // 23808
#define STAGE_BYTES (OFF_AL + KC * ASTR)       // 26624 (x2 stages = 53248)
#define VOL_BYTES (MT * VOL_STRIDE * 4)        // 82432
#define SMEM_BYTES (VOL_BYTES)                 // vol overlays both stages

static __device__ __forceinline__ uint32_t smem_u32(const void* p) {
    uint32_t a;
    asm("{ .reg .u64 t; cvta.to.shared.u64 t, %1; cvt.u32.u64 %0, t; }" : "=r"(a) : "l"(p));
    return a;
}

static __device__ __forceinline__ void ldsm4t(uint32_t* r, uint32_t a) {
    asm volatile("ldmatrix.sync.aligned.m8n8.x4.trans.shared.b16 {%0,%1,%2,%3}, [%4];"
                 : "=r"(r[0]), "=r"(r[1]), "=r"(r[2]), "=r"(r[3]) : "r"(a));
}
static __device__ __forceinline__ void ldsm2t(uint32_t* r, uint32_t a) {
    asm volatile("ldmatrix.sync.aligned.m8n8.x2.trans.shared.b16 {%0,%1}, [%2];"
                 : "=r"(r[0]), "=r"(r[1]) : "r"(a));
}
static __device__ __forceinline__ void mma16816(float* d, const uint32_t* a, const uint32_t* b) {
    asm volatile("mma.sync.aligned.m16n8k16.row.col.f32.bf16.bf16.f32 "
                 "{%0,%1,%2,%3}, {%4,%5,%6,%7}, {%8,%9}, {%0,%1,%2,%3};"
                 : "+f"(d[0]), "+f"(d[1]), "+f"(d[2]), "+f"(d[3])
                 : "r"(a[0]), "r"(a[1]), "r"(a[2]), "r"(a[3]), "r"(b[0]), "r"(b[1]));
}

// float4 -> hi (exact bf16 truncation) + lo (bf16 residual); two STS.64.
static __device__ __forceinline__ void cvt_sts(uint32_t hi_a, uint32_t lo_a, float4 x) {
    uint32_t u0 = __float_as_uint(x.x), u1 = __float_as_uint(x.y);
    uint32_t u2 = __float_as_uint(x.z), u3 = __float_as_uint(x.w);
    uint32_t h0, h1;
    asm("prmt.b32 %0, %1, %2, 0x7632;" : "=r"(h0) : "r"(u0), "r"(u1));
    asm("prmt.b32 %0, %1, %2, 0x7632;" : "=r"(h1) : "r"(u2), "r"(u3));
    float f0 = x.x - __uint_as_float(u0 & 0xffff0000u);
    float f1 = x.y - __uint_as_float(u1 & 0xffff0000u);
    float f2 = x.z - __uint_as_float(u2 & 0xffff0000u);
    float f3 = x.w - __uint_as_float(u3 & 0xffff0000u);
    uint32_t l0, l1;
    asm("cvt.rn.bf16x2.f32 %0, %1, %2;" : "=r"(l0) : "f"(f1), "f"(f0));
    asm("cvt.rn.bf16x2.f32 %0, %1, %2;" : "=r"(l1) : "f"(f3), "f"(f2));
    asm volatile("st.shared.v2.b32 [%0], {%1,%2};" :: "r"(hi_a), "r"(h0), "r"(h1) : "memory");
    asm volatile("st.shared.v2.b32 [%0], {%1,%2};" :: "r"(lo_a), "r"(l0), "r"(l1) : "memory");
}

__device__ __forceinline__ float pooled(const float* __restrict__ row, int i, int lvl, int Wl) {
    if (i < 0 || i >= Wl) return 0.0f;
    const int sz = 1 << lvl;
    const float* p = row + (i << lvl);
    float s = 0.0f;
#pragma unroll 8
    for (int k = 0; k < sz; ++k) s += p[k];
    return s * (1.0f / (float)sz);
}

__global__ void __launch_bounds__(NTH)
corr_hmma_kernel(const float* __restrict__ fmap1, const float* __restrict__ fmap2,
                 const float* __restrict__ cents, float* __restrict__ out) {
    extern __shared__ char smem[];
    const uint32_t sb = smem_u32(smem);
    const int t = threadIdx.x, wid = t >> 5, lid = t & 31;
    const int q0 = blockIdx.x * MT, h = blockIdx.y, b = blockIdx.z;

    // ---- load mapping: thread -> (channel-in-chunk, float4 position) ----
    const int ch  = t >> 4;   // 0..15
    const int pos = t & 15;   // 0..15
    const float* Ag = fmap1 + ((size_t)b * CC + ch) * HW + (size_t)h * WW + q0 + 4 * pos;
    const float* Bg = fmap2 + ((size_t)b * CC + ch) * HW + (size_t)h * WW + 4 * pos;

    // ---- per-lane ldmatrix offsets ----
    const int r8 = lid & 7, tl = lid >> 3;
    const uint32_t laneA = (uint32_t)((r8 + 8 * (tl >> 1)) * ASTR + (tl & 1) * 16);
    const uint32_t laneB = (uint32_t)((r8 + 8 * (tl & 1)) * BSTR + (tl >> 1) * 16);
    const uint32_t nbase = (uint32_t)(80 * wid);  // n = 40*wid

    const uint32_t sts_ah = sb + OFF_AH + (uint32_t)(ch * ASTR + 8 * pos);
    const uint32_t sts_al = sb + OFF_AL + (uint32_t)(ch * ASTR + 8 * pos);
    const uint32_t sts_bh = sb + OFF_BH + (uint32_t)(ch * BSTR + 8 * pos);
    const uint32_t sts_bl = sb + OFF_BL + (uint32_t)(ch * BSTR + 8 * pos);

    float acc[4][5][4];
#pragma unroll
    for (int i = 0; i < 4; ++i)
#pragma unroll
        for (int j = 0; j < 5; ++j)
#pragma unroll
            for (int k2 = 0; k2 < 4; ++k2) acc[i][j][k2] = 0.0f;

    float4 ra, rb[5];
    // chunk 0: load + stage into buf0
    ra = *(const float4*)Ag;
#pragma unroll
    for (int j = 0; j < 5; ++j) rb[j] = *(const float4*)(Bg + 64 * j);
    cvt_sts(sts_ah, sts_al, ra);
#pragma unroll
    for (int j = 0; j < 5; ++j) cvt_sts(sts_bh + 128u * j, sts_bl + 128u * j, rb[j]);
    __syncthreads();
    // prefetch chunk 1
    {
        const size_t o = (size_t)KC * HW;
        ra = *(const float4*)(Ag + o);
#pragma unroll
        for (int j = 0; j < 5; ++j) rb[j] = *(const float4*)(Bg + o + 64 * j);
    }

    for (int kc = 0; kc < NCHUNK; ++kc) {
        const uint32_t cur = sb + (uint32_t)((kc & 1) * STAGE_BYTES);
        const uint32_t nxt = (uint32_t)(((kc + 1) & 1) * STAGE_BYTES);

        // ---- fragment loads for this chunk (13 ldsm, each plane once) ----
        uint32_t ah[4][4], al[4][4], bh[10], bl[10];
        {
            const uint32_t abh = cur + OFF_AH + laneA;
            const uint32_t abl = cur + OFF_AL + laneA;
#pragma unroll
            for (int i = 0; i < 4; ++i) {
                ldsm4t(ah[i], abh + 32u * i);
                ldsm4t(al[i], abl + 32u * i);
            }
            const uint32_t bbh = cur + OFF_BH + laneB + nbase;
            const uint32_t bbl = cur + OFF_BL + laneB + nbase;
            ldsm4t(bh + 0, bbh); ldsm4t(bh + 4, bbh + 32u); ldsm2t(bh + 8, bbh + 64u);
            ldsm4t(bl + 0, bbl); ldsm4t(bl + 4, bbl + 32u); ldsm2t(bl + 8, bbl + 64u);
        }

        // ---- stage chunk kc+1 into opposite buffer (drains under MMAs) ----
        if (kc + 1 < NCHUNK) {
            cvt_sts(sts_ah + nxt, sts_al + nxt, ra);
#pragma unroll
            for (int j = 0; j < 5; ++j)
                cvt_sts(sts_bh + nxt + 128u * j, sts_bl + nxt + 128u * j, rb[j]);
            // ---- issue LDGs for chunk kc+2 (covered by MMA phase) ----
            if (kc + 2 < NCHUNK) {
                const size_t o = (size_t)(kc + 2) * KC * HW;
                ra = *(const float4*)(Ag + o);
#pragma unroll
                for (int j = 0; j < 5; ++j) rb[j] = *(const float4*)(Bg + o + 64 * j);
            }
        }

        // ---- 60 MMAs: (Ah,Bh), (Ah,Bl), (Al,Bh) ----
#pragma unroll
        for (int i = 0; i < 4; ++i)
#pragma unroll
            for (int j = 0; j < 5; ++j) {
                mma16816(acc[i][j], ah[i], bh + 2 * j);
                mma16816(acc[i][j], ah[i], bl + 2 * j);
                mma16816(acc[i][j], al[i], bh + 2 * j);
            }

        __syncthreads();  // all frags read + all STS drained before buffer reuse
    }

    // ---- accumulators -> vol (overlays stage smem) ----
    float* vol = (float*)smem;
    {
        const int mr = lid >> 2, nc0 = 2 * (lid & 3);
        const float s = 0.0625f;  // 1/sqrt(256)
#pragma unroll
        for (int i = 0; i < 4; ++i)
#pragma unroll
            for (int j = 0; j < 5; ++j) {
                const int q = 16 * i + mr, v = 40 * wid + 8 * j + nc0;
                *(float2*)&vol[q * VOL_STRIDE + v] =
                    make_float2(acc[i][j][0] * s, acc[i][j][1] * s);
                *(float2*)&vol[(q + 8) * VOL_STRIDE + v] =
                    make_float2(acc[i][j][2] * s, acc[i][j][3] * s);
            }
    }
    __syncthreads();

    // ---- pyramid sampling: 64 q x 36 ch, 9 outputs/thread ----
    const int q = t & 63, grp = t >> 6;
    const float cent = cents[((size_t)b * HH + h) * WW + q0 + q];
    const float* row = vol + q * VOL_STRIDE;
#pragma unroll
    for (int rep = 0; rep < 9; ++rep) {
        const int chn = grp + 4 * rep;
        const int lvl = chn / 9, tap = chn - 9 * lvl;
        const int Wl = WW >> lvl;
        const float x  = cent * (1.0f / (float)(1 << lvl)) + (float)(tap - RAD);
        const float x0 = floorf(x);
        const float tt = x - x0;
        const int   i0 = (int)x0;
        const float p0 = pooled(row, i0, lvl, Wl);
        const float p1 = pooled(row, i0 + 1, lvl, Wl);
        out[(((size_t)b * NCH + chn) * HH + h) * WW + q0 + q] = p0 * (1.0f - tt) + p1 * tt;
    }
}

extern "C" void kernel_launch(void* const* d_in, const int* in_sizes, int n_in,
                              void* d_out, int out_size) {
    const float* fmap1 = (const float*)d_in[0];
    const float* fmap2 = (const float*)d_in[1];
    const float* cents = (const float*)d_in[2];
    float* out = (float*)d_out;

    cudaFuncSetAttribute(corr_hmma_kernel,
                         cudaFuncAttributeMaxDynamicSharedMemorySize, SMEM_BYTES);

    dim3 grid(WW / MT, HH, BB);  // (5, 96, 4)
    corr_hmma_kernel<<<grid, NTH, SMEM_BYTES>>>(fmap1, fmap2, cents, out);
}